// round 7
// baseline (speedup 1.0000x reference)
#include <cuda_runtime.h>
#include <cuda_bf16.h>

#define L 4
#define B 128
#define T 1024
#define NI 512
#define H 512
#define G 2048
#define BH (B*H)

#define NBLK 128
#define NTHR 512

// ---- smem layout (bytes) ----
// W: 64 rows x 512 k, hi/lo planes, row stride 1040B
#define WS_HI 0
#define WS_LO 66560
// x-phase stage: 2 buffers x (hi+lo planes), plane = 128 rows x 144B
#define PS 133120
#define PLANE 18432
#define BUFSTRIDE 36864
// recurrent stage: 32 rows x 512 k hi/lo planes, row stride 1040B
#define RS 133120
#define RPLANE 33280
// gates: 2 buffers of 64 x 32 f32, row stride 34
#define GS2 199680
#define GBUF (64*34)
#define SMEM_BYTES 217088

// ---- device scratch ----
__device__ unsigned g_x_pack[(size_t)B * T * NI];
__device__ unsigned g_seq_pack[(size_t)T * BH];
__device__ unsigned g_h0_pack[(size_t)L * BH];
__device__ float g_gx[(size_t)B * T * G];           // [b][t][gate]
__device__ unsigned long long g_flags[NBLK];

__device__ __forceinline__ void flag_release(unsigned long long* p, unsigned long long v) {
    asm volatile("st.release.gpu.global.u64 [%0], %1;" :: "l"(p), "l"(v) : "memory");
}
__device__ __forceinline__ unsigned long long flag_acquire(const unsigned long long* p) {
    unsigned long long v;
    asm volatile("ld.acquire.gpu.global.u64 %0, [%1];" : "=l"(v) : "l"(p) : "memory");
    return v;
}

// global barrier (prologue only)
__device__ __forceinline__ void gbar_all(unsigned long long ep) {
    __syncthreads();
    if (threadIdx.x == 0) flag_release(&g_flags[blockIdx.x], ep);
    if (threadIdx.x < NBLK) {
        while (flag_acquire(&g_flags[threadIdx.x]) < ep) { }
    }
    __syncthreads();
}

// group barrier: 32 blocks sharing a batch group
__device__ __forceinline__ void gbar_grp(unsigned long long ep, int grp) {
    __syncthreads();
    if (threadIdx.x == 0) flag_release(&g_flags[blockIdx.x], ep);
    if (threadIdx.x < 32) {
        while (flag_acquire(&g_flags[grp * 32 + threadIdx.x]) < ep) { }
    }
    __syncthreads();
}

__device__ __forceinline__ unsigned packf(float v) {
    __nv_bfloat16 h = __float2bfloat16(v);
    float hf = __bfloat162float(h);
    __nv_bfloat16 lo = __float2bfloat16(v - hf);
    unsigned short uh = *(unsigned short*)&h;
    unsigned short ul = *(unsigned short*)&lo;
    return ((unsigned)ul << 16) | (unsigned)uh;
}

__device__ __forceinline__ void ldsm4(unsigned r[4], unsigned addr) {
    asm volatile("ldmatrix.sync.aligned.m8n8.x4.shared.b16 {%0,%1,%2,%3}, [%4];"
                 : "=r"(r[0]), "=r"(r[1]), "=r"(r[2]), "=r"(r[3]) : "r"(addr));
}

__device__ __forceinline__ void mma16816(float c[4], const unsigned a[4],
                                         unsigned b0, unsigned b1) {
    asm volatile(
        "mma.sync.aligned.m16n8k16.row.col.f32.bf16.bf16.f32 "
        "{%0,%1,%2,%3}, {%4,%5,%6,%7}, {%8,%9}, {%0,%1,%2,%3};"
        : "+f"(c[0]), "+f"(c[1]), "+f"(c[2]), "+f"(c[3])
        : "r"(a[0]), "r"(a[1]), "r"(a[2]), "r"(a[3]), "r"(b0), "r"(b1));
}

__device__ __forceinline__ float sigf(float x) { return 1.0f / (1.0f + __expf(-x)); }
__device__ __forceinline__ float tanhg(float x) { return 2.0f / (1.0f + __expf(-2.0f * x)) - 1.0f; }

__device__ __forceinline__ void stage_store(char* bufHi, unsigned off, uint4 p, int plane) {
    unsigned h0_ = __byte_perm(p.x, p.y, 0x5410);
    unsigned h1_ = __byte_perm(p.z, p.w, 0x5410);
    unsigned l0_ = __byte_perm(p.x, p.y, 0x7632);
    unsigned l1_ = __byte_perm(p.z, p.w, 0x7632);
    *(uint2*)(bufHi + off) = make_uint2(h0_, h1_);
    *(uint2*)(bufHi + plane + off) = make_uint2(l0_, l1_);
}

__global__ void __launch_bounds__(NTHR, 1)
lstm_kernel(const float* __restrict__ x,
            const float* __restrict__ h0,
            const float* __restrict__ c0,
            const float* __restrict__ w_ih,
            const float* __restrict__ w_hh,
            const float* __restrict__ b_ih,
            const float* __restrict__ b_hh,
            float* __restrict__ out) {
    extern __shared__ char sm[];
    const unsigned sbase = (unsigned)__cvta_generic_to_shared(sm);

    const int tid = threadIdx.x, bid = blockIdx.x;
    const int lane = tid & 31, warp = tid >> 5;

    unsigned long long ep = g_flags[bid];

    // ---------------- prologue: pack x, h0 ----------------
    {
        const size_t gt0 = (size_t)bid * NTHR + tid, gs = (size_t)NBLK * NTHR;
        const float4* xs = (const float4*)x;
        const size_t nx = (size_t)B * T * NI / 4;
        for (size_t i = gt0; i < nx; i += gs) {
            float4 v = __ldg(xs + i);
            ((uint4*)g_x_pack)[i] = make_uint4(packf(v.x), packf(v.y), packf(v.z), packf(v.w));
        }
        const float4* hs = (const float4*)h0;
        const size_t nh = (size_t)L * BH / 4;
        for (size_t i = gt0; i < nh; i += gs) {
            float4 v = __ldg(hs + i);
            ((uint4*)g_h0_pack)[i] = make_uint4(packf(v.x), packf(v.y), packf(v.z), packf(v.w));
        }
    }
    gbar_all(++ep);

    const int gt = bid & 31;    // gate/h tile
    const int grp = bid >> 5;   // batch group (32 batches)

    const int wg = warp >> 2, wsub = warp & 3;   // wsub = n-split (x-phase) / k-split (recurrent)
    const unsigned wA = sbase + WS_HI + (unsigned)((wg * 16 + (lane & 15)) * 1040 + (lane >> 4) * 16);
    const unsigned wAlo = wA + (WS_LO - WS_HI);
    const unsigned pBx_rel = (unsigned)((wsub * 32 + (lane & 7) + ((lane >> 4) << 3)) * 144
                                        + ((lane >> 3) & 1) * 16);
    // recurrent B frag base: batch rows 0..7 + ntile offset in loop; k base = ks*256B
    const unsigned pBr0 = sbase + RS + (unsigned)((lane & 7) * 1040 + (lane >> 3) * 16 + wsub * 256);
    const unsigned wAr = wA + wsub * 256;       // this warp's K128 range within W rows
    const unsigned wArlo = wAr + (WS_LO - WS_HI);

    const int lh = tid & 15, lb = tid >> 4;
    const int eb = grp * 32 + lb;
    const int egh = gt * 16 + lh;

    for (int l = 0; l < L; ++l) {
        // ================= x-phase: gx = W_ih * input_seq =================
        for (int it = tid; it < 64 * 128; it += NTHR) {
            int r = it >> 7, c4 = it & 127;
            float4 v = __ldg((const float4*)(w_ih + ((size_t)l * G + gt * 64 + r) * 512) + c4);
            unsigned p0 = packf(v.x), p1 = packf(v.y), p2 = packf(v.z), p3 = packf(v.w);
            *(uint2*)(sm + WS_HI + r * 1040 + c4 * 8) =
                make_uint2(__byte_perm(p0, p1, 0x5410), __byte_perm(p2, p3, 0x5410));
            *(uint2*)(sm + WS_LO + r * 1040 + c4 * 8) =
                make_uint2(__byte_perm(p0, p1, 0x7632), __byte_perm(p2, p3, 0x7632));
        }
        __syncthreads();

        {
            const int srow = tid >> 2, ssg = tid & 3;
            for (int m = 0; m < 256; ++m) {
                const int bb = grp * 32 + (m >> 3);
                const int t0 = (m & 7) * 128;

                const unsigned* rowp;
                if (l == 0) rowp = g_x_pack + (((size_t)bb << 10) + (size_t)(t0 + srow)) * 512;
                else        rowp = g_seq_pack + ((size_t)((t0 + srow) * 128 + bb)) * 512;

                float acc[4][4];
                #pragma unroll
                for (int f = 0; f < 4; ++f)
                    #pragma unroll
                    for (int q = 0; q < 4; ++q) acc[f][q] = 0.f;

                uint4 rg[4];
                #pragma unroll
                for (int q = 0; q < 4; ++q) rg[q] = __ldcg((const uint4*)rowp + ssg + 4 * q);
                #pragma unroll
                for (int q = 0; q < 4; ++q)
                    stage_store(sm + PS, srow * 144 + (ssg + 4 * q) * 8, rg[q], PLANE);
                #pragma unroll
                for (int q = 0; q < 4; ++q) rg[q] = __ldcg((const uint4*)rowp + 16 + ssg + 4 * q);
                __syncthreads();

                #pragma unroll 1
                for (int c = 0; c < 8; ++c) {
                    if (c < 7) {
                        char* bufHi = sm + PS + ((c + 1) & 1) * BUFSTRIDE;
                        #pragma unroll
                        for (int q = 0; q < 4; ++q)
                            stage_store(bufHi, srow * 144 + (ssg + 4 * q) * 8, rg[q], PLANE);
                    }
                    if (c < 6) {
                        #pragma unroll
                        for (int q = 0; q < 4; ++q)
                            rg[q] = __ldcg((const uint4*)rowp + (c + 2) * 16 + ssg + 4 * q);
                    }
                    const unsigned bufo = sbase + PS + (c & 1) * BUFSTRIDE;
                    #pragma unroll
                    for (int q = 0; q < 4; ++q) {
                        unsigned ah[4], al[4];
                        ldsm4(ah, wA + c * 128 + q * 32);
                        ldsm4(al, wAlo + c * 128 + q * 32);
                        #pragma unroll
                        for (int u = 0; u < 2; ++u) {
                            unsigned bh[4], bl[4];
                            unsigned ba = bufo + pBx_rel + u * 2304 + q * 32;
                            ldsm4(bh, ba);
                            ldsm4(bl, ba + PLANE);
                            mma16816(acc[2 * u],     ah, bh[0], bh[1]);
                            mma16816(acc[2 * u],     al, bh[0], bh[1]);
                            mma16816(acc[2 * u],     ah, bl[0], bl[1]);
                            mma16816(acc[2 * u + 1], ah, bh[2], bh[3]);
                            mma16816(acc[2 * u + 1], al, bh[2], bh[3]);
                            mma16816(acc[2 * u + 1], ah, bl[2], bl[3]);
                        }
                    }
                    __syncthreads();
                }

                const size_t cb = ((size_t)bb << 10) + (size_t)t0;
                const int gr0 = gt * 64 + wg * 16 + (lane >> 2);
                #pragma unroll
                for (int f = 0; f < 4; ++f) {
                    int u = f >> 1, v2 = f & 1;
                    int tt = wsub * 32 + u * 16 + v2 * 8 + (lane & 3) * 2;
                    float* p = g_gx + (cb + tt) * G + gr0;
                    __stcg(p, acc[f][0]);
                    __stcg(p + G, acc[f][1]);
                    __stcg(p + 8, acc[f][2]);
                    __stcg(p + G + 8, acc[f][3]);
                }
            }
        }
        gbar_grp(++ep, grp);

        // ================= recurrent phase =================
        for (int it = tid; it < 64 * 128; it += NTHR) {
            int r = it >> 7, c4 = it & 127;
            int grow = (r >> 4) * 512 + gt * 16 + (r & 15);
            float4 v = __ldg((const float4*)(w_hh + ((size_t)l * G + grow) * 512) + c4);
            unsigned p0 = packf(v.x), p1 = packf(v.y), p2 = packf(v.z), p3 = packf(v.w);
            *(uint2*)(sm + WS_HI + r * 1040 + c4 * 8) =
                make_uint2(__byte_perm(p0, p1, 0x5410), __byte_perm(p2, p3, 0x5410));
            *(uint2*)(sm + WS_LO + r * 1040 + c4 * 8) =
                make_uint2(__byte_perm(p0, p1, 0x7632), __byte_perm(p2, p3, 0x7632));
        }
        __syncthreads();

        float bias[4];
        #pragma unroll
        for (int g = 0; g < 4; ++g)
            bias[g] = __ldg(b_ih + (size_t)l * G + g * 512 + egh)
                    + __ldg(b_hh + (size_t)l * G + g * 512 + egh);
        float creg = __ldg(c0 + (size_t)l * BH + (size_t)eb * 512 + egh);
        const float* gx_base = g_gx + ((size_t)eb << 10) * G + egh;

        const int hrow = tid >> 4, hsg = tid & 15;
        float* const gbuf = (float*)(sm + GS2) + (wsub & 1) * GBUF;
        const int gr0 = wg * 16 + (lane >> 2);
        const int colb = (lane & 3) * 2;

        for (int t = 0; t < T; ++t) {
            const float* gxt = gx_base + (size_t)t * G;
            float gx0 = __ldcg(gxt);
            float gx1 = __ldcg(gxt + 512);
            float gx2 = __ldcg(gxt + 1024);
            float gx3 = __ldcg(gxt + 1536);

            const unsigned* rowp;
            if (t == 0) rowp = g_h0_pack + ((size_t)(l * 128 + grp * 32 + hrow)) * 512;
            else        rowp = g_seq_pack + ((size_t)((t - 1) * 128 + grp * 32 + hrow)) * 512;

            uint4 hrg[8];
            #pragma unroll
            for (int c = 0; c < 8; ++c)
                hrg[c] = __ldcg((const uint4*)rowp + c * 16 + hsg);
            #pragma unroll
            for (int c = 0; c < 8; ++c)
                stage_store(sm + RS, hrow * 1040 + (c * 16 + hsg) * 8, hrg[c], RPLANE);
            __syncthreads();

            // warp = (wg m-stripe, wsub K-split); computes m16 x n32 x K128
            float a0[4][4], a1[4][4];
            #pragma unroll
            for (int nt = 0; nt < 4; ++nt)
                #pragma unroll
                for (int q = 0; q < 4; ++q) { a0[nt][q] = 0.f; a1[nt][q] = 0.f; }

            #pragma unroll
            for (int c = 0; c < 4; ++c) {
                unsigned ah0[4], ah1[4], al0[4], al1[4];
                ldsm4(ah0, wAr + c * 64);
                ldsm4(ah1, wAr + c * 64 + 32);
                ldsm4(al0, wArlo + c * 64);
                ldsm4(al1, wArlo + c * 64 + 32);
                #pragma unroll
                for (int nt = 0; nt < 4; ++nt) {
                    unsigned bh[4], bl[4];
                    unsigned ba = pBr0 + nt * (8 * 1040) + c * 64;
                    ldsm4(bh, ba);
                    ldsm4(bl, ba + RPLANE);
                    mma16816(a0[nt], ah0, bh[0], bh[1]);
                    mma16816(a1[nt], al0, bh[0], bh[1]);
                    mma16816(a1[nt], ah0, bl[0], bl[1]);
                    mma16816(a0[nt], ah1, bh[2], bh[3]);
                    mma16816(a1[nt], al1, bh[2], bh[3]);
                    mma16816(a1[nt], ah1, bl[2], bl[3]);
                }
            }

            // two-phase K-split reduction into 2 gate buffers
            if (wsub < 2) {
                #pragma unroll
                for (int nt = 0; nt < 4; ++nt) {
                    *(float2*)&gbuf[gr0 * 34 + nt * 8 + colb] =
                        make_float2(a0[nt][0] + a1[nt][0], a0[nt][1] + a1[nt][1]);
                    *(float2*)&gbuf[(gr0 + 8) * 34 + nt * 8 + colb] =
                        make_float2(a0[nt][2] + a1[nt][2], a0[nt][3] + a1[nt][3]);
                }
            }
            __syncthreads();
            if (wsub >= 2) {
                #pragma unroll
                for (int nt = 0; nt < 4; ++nt) {
                    float2 v0 = *(float2*)&gbuf[gr0 * 34 + nt * 8 + colb];
                    v0.x += a0[nt][0] + a1[nt][0];
                    v0.y += a0[nt][1] + a1[nt][1];
                    *(float2*)&gbuf[gr0 * 34 + nt * 8 + colb] = v0;
                    float2 v1 = *(float2*)&gbuf[(gr0 + 8) * 34 + nt * 8 + colb];
                    v1.x += a0[nt][2] + a1[nt][2];
                    v1.y += a0[nt][3] + a1[nt][3];
                    *(float2*)&gbuf[(gr0 + 8) * 34 + nt * 8 + colb] = v1;
                }
            }
            __syncthreads();

            // elementwise
            {
                const float* gb0 = (const float*)(sm + GS2);
                const float* gb1 = gb0 + GBUF;
                float v0 = bias[0] + gb0[lh * 34 + lb]          + gb1[lh * 34 + lb]          + gx0;
                float v1 = bias[1] + gb0[(16 + lh) * 34 + lb]   + gb1[(16 + lh) * 34 + lb]   + gx1;
                float v2 = bias[2] + gb0[(32 + lh) * 34 + lb]   + gb1[(32 + lh) * 34 + lb]   + gx2;
                float v3 = bias[3] + gb0[(48 + lh) * 34 + lb]   + gb1[(48 + lh) * 34 + lb]   + gx3;
                float ig = sigf(v0), fg = sigf(v1), gg = tanhg(v2), og = sigf(v3);
                creg = fmaf(fg, creg, ig * gg);
                float hv = og * tanhg(creg);
                g_seq_pack[((size_t)t * 128 + eb) * 512 + egh] = packf(hv);
                if (t == T - 1)
                    out[(size_t)l * BH + (size_t)eb * 512 + egh] = creg;
            }
            gbar_grp(++ep, grp);
        }
    }
}

extern "C" void kernel_launch(void* const* d_in, const int* in_sizes, int n_in,
                              void* d_out, int out_size) {
    const float* x    = (const float*)d_in[0];
    const float* h0   = (const float*)d_in[1];
    const float* c0   = (const float*)d_in[2];
    const float* w_ih = (const float*)d_in[3];
    const float* w_hh = (const float*)d_in[4];
    const float* b_ih = (const float*)d_in[5];
    const float* b_hh = (const float*)d_in[6];
    float* out = (float*)d_out;

    cudaFuncSetAttribute(lstm_kernel,
                         cudaFuncAttributeMaxDynamicSharedMemorySize, SMEM_BYTES);
    lstm_kernel<<<NBLK, NTHR, SMEM_BYTES>>>(x, h0, c0, w_ih, w_hh, b_ih, b_hh, out);
}

// round 8
// speedup vs baseline: 1.4866x; 1.4866x over previous
#include <cuda_runtime.h>
#include <cuda_bf16.h>

#define L 4
#define B 128
#define T 1024
#define NI 512
#define H 512
#define G 2048
#define BH (B*H)

#define NBLK 128
#define NTHR 512

// ---- smem layout (bytes) ----
// W: 64 rows x 512 k, hi/lo bf16 planes, row stride 1040B
#define WS_HI 0
#define WS_LO 66560
// x-phase stage: 2 buffers x (hi+lo planes), plane = 128 rows x 144B
#define PS 133120
#define PLANE 18432
#define BUFSTRIDE 36864
// recurrent stage: 32 rows x 512 k hi/lo planes, row stride 1040B
#define RS 133120
#define RPLANE 33280
// gates tile 64 x 32 f32, stride 33
#define GS 206848
#define SMEM_BYTES 215296

// ---- device scratch ----
__device__ unsigned g_x_pack[(size_t)B * T * NI];
__device__ unsigned g_seq_pack[(size_t)T * BH];
__device__ unsigned g_h0_pack[(size_t)L * BH];
__device__ float g_gx[(size_t)B * T * G];           // [t][b][gate]  (coalesced x-phase stores)
__device__ unsigned long long g_flags[NBLK];

__device__ __forceinline__ unsigned long long ldvol(const unsigned long long* p) {
    unsigned long long v;
    asm volatile("ld.volatile.global.u64 %0, [%1];" : "=l"(v) : "l"(p));
    return v;
}

// global barrier (prologue only)
__device__ __forceinline__ void gbar_all(unsigned long long ep) {
    __syncthreads();
    __threadfence();
    if (threadIdx.x == 0) atomicExch(&g_flags[blockIdx.x], ep);
    if (threadIdx.x < NBLK) {
        while (ldvol(&g_flags[threadIdx.x]) < ep) { }
    }
    __threadfence();
    __syncthreads();
}

// group barrier: 32 blocks sharing a batch group
__device__ __forceinline__ void gbar_grp(unsigned long long ep, int grp) {
    __syncthreads();
    __threadfence();
    if (threadIdx.x == 0) atomicExch(&g_flags[blockIdx.x], ep);
    if (threadIdx.x < 32) {
        while (ldvol(&g_flags[grp * 32 + threadIdx.x]) < ep) { }
    }
    __threadfence();
    __syncthreads();
}

__device__ __forceinline__ unsigned packf(float v) {
    __nv_bfloat16 h = __float2bfloat16(v);
    float hf = __bfloat162float(h);
    __nv_bfloat16 lo = __float2bfloat16(v - hf);
    unsigned short uh = *(unsigned short*)&h;
    unsigned short ul = *(unsigned short*)&lo;
    return ((unsigned)ul << 16) | (unsigned)uh;
}

__device__ __forceinline__ void ldsm4(unsigned r[4], unsigned addr) {
    asm volatile("ldmatrix.sync.aligned.m8n8.x4.shared.b16 {%0,%1,%2,%3}, [%4];"
                 : "=r"(r[0]), "=r"(r[1]), "=r"(r[2]), "=r"(r[3]) : "r"(addr));
}

__device__ __forceinline__ void mma16816(float c[4], const unsigned a[4],
                                         unsigned b0, unsigned b1) {
    asm volatile(
        "mma.sync.aligned.m16n8k16.row.col.f32.bf16.bf16.f32 "
        "{%0,%1,%2,%3}, {%4,%5,%6,%7}, {%8,%9}, {%0,%1,%2,%3};"
        : "+f"(c[0]), "+f"(c[1]), "+f"(c[2]), "+f"(c[3])
        : "r"(a[0]), "r"(a[1]), "r"(a[2]), "r"(a[3]), "r"(b0), "r"(b1));
}

__device__ __forceinline__ float sigf(float x) { return 1.0f / (1.0f + __expf(-x)); }
__device__ __forceinline__ float tanhg(float x) { return 2.0f / (1.0f + __expf(-2.0f * x)) - 1.0f; }

__device__ __forceinline__ void stage_store(char* bufHi, unsigned off, uint4 p, int plane) {
    unsigned h0_ = __byte_perm(p.x, p.y, 0x5410);
    unsigned h1_ = __byte_perm(p.z, p.w, 0x5410);
    unsigned l0_ = __byte_perm(p.x, p.y, 0x7632);
    unsigned l1_ = __byte_perm(p.z, p.w, 0x7632);
    *(uint2*)(bufHi + off) = make_uint2(h0_, h1_);
    *(uint2*)(bufHi + plane + off) = make_uint2(l0_, l1_);
}

__global__ void __launch_bounds__(NTHR, 1)
lstm_kernel(const float* __restrict__ x,
            const float* __restrict__ h0,
            const float* __restrict__ c0,
            const float* __restrict__ w_ih,
            const float* __restrict__ w_hh,
            const float* __restrict__ b_ih,
            const float* __restrict__ b_hh,
            float* __restrict__ out) {
    extern __shared__ char sm[];
    const unsigned sbase = (unsigned)__cvta_generic_to_shared(sm);
    float* const gates_s = (float*)(sm + GS);

    const int tid = threadIdx.x, bid = blockIdx.x;
    const int lane = tid & 31, warp = tid >> 5;

    unsigned long long ep = ldvol(&g_flags[bid]);

    // ---------------- prologue: pack x, h0 ----------------
    {
        const size_t gt0 = (size_t)bid * NTHR + tid, gs = (size_t)NBLK * NTHR;
        const float4* xs = (const float4*)x;
        const size_t nx = (size_t)B * T * NI / 4;
        for (size_t i = gt0; i < nx; i += gs) {
            float4 v = __ldg(xs + i);
            ((uint4*)g_x_pack)[i] = make_uint4(packf(v.x), packf(v.y), packf(v.z), packf(v.w));
        }
        const float4* hs = (const float4*)h0;
        const size_t nh = (size_t)L * BH / 4;
        for (size_t i = gt0; i < nh; i += gs) {
            float4 v = __ldg(hs + i);
            ((uint4*)g_h0_pack)[i] = make_uint4(packf(v.x), packf(v.y), packf(v.z), packf(v.w));
        }
    }
    gbar_all(++ep);

    const int gt = bid & 31;    // gate/h tile
    const int grp = bid >> 5;   // batch group (32 batches)

    const int wg = warp >> 2, wsub = warp & 3;
    const unsigned wA = sbase + WS_HI + (unsigned)((wg * 16 + (lane & 15)) * 1040 + (lane >> 4) * 16);
    const unsigned wAlo = wA + (WS_LO - WS_HI);
    const unsigned pBx_rel = (unsigned)((wsub * 32 + (lane & 7) + ((lane >> 4) << 3)) * 144
                                        + ((lane >> 3) & 1) * 16);
    // recurrent B frag: batch rows, stride 1040
    const unsigned pBr = sbase + RS + (unsigned)((wsub * 8 + (lane & 7)) * 1040 + (lane >> 3) * 16);

    const int lh = tid & 15, lb = tid >> 4;
    const int eb = grp * 32 + lb;
    const int egh = gt * 16 + lh;

    for (int l = 0; l < L; ++l) {
        // ================= x-phase: gx = W_ih * input_seq =================
        for (int it = tid; it < 64 * 128; it += NTHR) {
            int r = it >> 7, c4 = it & 127;
            float4 v = __ldg((const float4*)(w_ih + ((size_t)l * G + gt * 64 + r) * 512) + c4);
            unsigned p0 = packf(v.x), p1 = packf(v.y), p2 = packf(v.z), p3 = packf(v.w);
            *(uint2*)(sm + WS_HI + r * 1040 + c4 * 8) =
                make_uint2(__byte_perm(p0, p1, 0x5410), __byte_perm(p2, p3, 0x5410));
            *(uint2*)(sm + WS_LO + r * 1040 + c4 * 8) =
                make_uint2(__byte_perm(p0, p1, 0x7632), __byte_perm(p2, p3, 0x7632));
        }
        __syncthreads();

        {
            const int srow = tid >> 2, ssg = tid & 3;
            for (int m = 0; m < 256; ++m) {
                const int bb = grp * 32 + (m >> 3);
                const int t0 = (m & 7) * 128;

                const unsigned* rowp;
                if (l == 0) rowp = g_x_pack + (((size_t)bb << 10) + (size_t)(t0 + srow)) * 512;
                else        rowp = g_seq_pack + ((size_t)((t0 + srow) * 128 + bb)) * 512;

                float acc[4][4];
                #pragma unroll
                for (int f = 0; f < 4; ++f)
                    #pragma unroll
                    for (int q = 0; q < 4; ++q) acc[f][q] = 0.f;

                uint4 rg[4];
                #pragma unroll
                for (int q = 0; q < 4; ++q) rg[q] = __ldcg((const uint4*)rowp + ssg + 4 * q);
                #pragma unroll
                for (int q = 0; q < 4; ++q)
                    stage_store(sm + PS, srow * 144 + (ssg + 4 * q) * 8, rg[q], PLANE);
                #pragma unroll
                for (int q = 0; q < 4; ++q) rg[q] = __ldcg((const uint4*)rowp + 16 + ssg + 4 * q);
                __syncthreads();

                #pragma unroll 1
                for (int c = 0; c < 8; ++c) {
                    if (c < 7) {
                        char* bufHi = sm + PS + ((c + 1) & 1) * BUFSTRIDE;
                        #pragma unroll
                        for (int q = 0; q < 4; ++q)
                            stage_store(bufHi, srow * 144 + (ssg + 4 * q) * 8, rg[q], PLANE);
                    }
                    if (c < 6) {
                        #pragma unroll
                        for (int q = 0; q < 4; ++q)
                            rg[q] = __ldcg((const uint4*)rowp + (c + 2) * 16 + ssg + 4 * q);
                    }
                    const unsigned bufo = sbase + PS + (c & 1) * BUFSTRIDE;
                    #pragma unroll
                    for (int q = 0; q < 4; ++q) {
                        unsigned ah[4], al[4];
                        ldsm4(ah, wA + c * 128 + q * 32);
                        ldsm4(al, wAlo + c * 128 + q * 32);
                        #pragma unroll
                        for (int u = 0; u < 2; ++u) {
                            unsigned bh[4], bl[4];
                            unsigned ba = bufo + pBx_rel + u * 2304 + q * 32;
                            ldsm4(bh, ba);
                            ldsm4(bl, ba + PLANE);
                            mma16816(acc[2 * u],     ah, bh[0], bh[1]);
                            mma16816(acc[2 * u],     al, bh[0], bh[1]);
                            mma16816(acc[2 * u],     ah, bl[0], bl[1]);
                            mma16816(acc[2 * u + 1], ah, bh[2], bh[3]);
                            mma16816(acc[2 * u + 1], al, bh[2], bh[3]);
                            mma16816(acc[2 * u + 1], ah, bl[2], bl[3]);
                        }
                    }
                    __syncthreads();
                }

                // store gx tile: layout [t][b][gate] -> per-instr lanes write
                // 8 consecutive gate floats per t (full 32B sectors, no amplification)
                const int gr0g = gt * 64 + wg * 16 + (lane >> 2);
                #pragma unroll
                for (int f = 0; f < 4; ++f) {
                    int u = f >> 1, v2 = f & 1;
                    int tt = wsub * 32 + u * 16 + v2 * 8 + (lane & 3) * 2;
                    size_t base = ((size_t)(t0 + tt) * 128 + bb) * (size_t)G + gr0g;
                    __stcg(g_gx + base,                        acc[f][0]);
                    __stcg(g_gx + base + (size_t)128 * G,      acc[f][1]);   // t+1
                    __stcg(g_gx + base + 8,                    acc[f][2]);   // gate row +8
                    __stcg(g_gx + base + (size_t)128 * G + 8,  acc[f][3]);
                }
            }
        }
        gbar_grp(++ep, grp);

        // ================= recurrent phase =================
        for (int it = tid; it < 64 * 128; it += NTHR) {
            int r = it >> 7, c4 = it & 127;
            int grow = (r >> 4) * 512 + gt * 16 + (r & 15);
            float4 v = __ldg((const float4*)(w_hh + ((size_t)l * G + grow) * 512) + c4);
            unsigned p0 = packf(v.x), p1 = packf(v.y), p2 = packf(v.z), p3 = packf(v.w);
            *(uint2*)(sm + WS_HI + r * 1040 + c4 * 8) =
                make_uint2(__byte_perm(p0, p1, 0x5410), __byte_perm(p2, p3, 0x5410));
            *(uint2*)(sm + WS_LO + r * 1040 + c4 * 8) =
                make_uint2(__byte_perm(p0, p1, 0x7632), __byte_perm(p2, p3, 0x7632));
        }
        __syncthreads();

        float bias[4];
        #pragma unroll
        for (int g = 0; g < 4; ++g)
            bias[g] = __ldg(b_ih + (size_t)l * G + g * 512 + egh)
                    + __ldg(b_hh + (size_t)l * G + g * 512 + egh);
        float creg = __ldg(c0 + (size_t)l * BH + (size_t)eb * 512 + egh);
        // gx layout [t][b][gate]
        const float* gx_base = g_gx + (size_t)eb * G + egh;

        const int hrow = tid >> 4, hsg = tid & 15;  // 32 rows x 16 uint4 segs

        for (int t = 0; t < T; ++t) {
            // prefetch gx for EW (hides L2/DRAM latency under MMA phase)
            const float* gxt = gx_base + (size_t)t * (128 * G);
            float gx0 = __ldcg(gxt);
            float gx1 = __ldcg(gxt + 512);
            float gx2 = __ldcg(gxt + 1024);
            float gx3 = __ldcg(gxt + 1536);

            const unsigned* rowp;
            if (t == 0) rowp = g_h0_pack + ((size_t)(l * 128 + grp * 32 + hrow)) * 512;
            else        rowp = g_seq_pack + ((size_t)((t - 1) * 128 + grp * 32 + hrow)) * 512;

            uint4 hrg[8];
            #pragma unroll
            for (int c = 0; c < 8; ++c)
                hrg[c] = __ldcg((const uint4*)rowp + c * 16 + hsg);

            // stage whole 32x512 h tile (hi/lo), single sync
            #pragma unroll
            for (int c = 0; c < 8; ++c)
                stage_store(sm + RS, hrow * 1040 + (c * 16 + hsg) * 8, hrg[c], RPLANE);
            __syncthreads();

            float a0[4] = {0.f, 0.f, 0.f, 0.f}, a1[4] = {0.f, 0.f, 0.f, 0.f};
            #pragma unroll
            for (int c = 0; c < 8; ++c) {
                #pragma unroll
                for (int g2 = 0; g2 < 2; ++g2) {
                    unsigned bh[4], bl[4], ah0[4], ah1[4], al0[4], al1[4];
                    unsigned ba = pBr + c * 128 + g2 * 64;
                    ldsm4(bh, ba);
                    ldsm4(bl, ba + RPLANE);
                    ldsm4(ah0, wA + c * 128 + g2 * 64);
                    ldsm4(ah1, wA + c * 128 + g2 * 64 + 32);
                    ldsm4(al0, wAlo + c * 128 + g2 * 64);
                    ldsm4(al1, wAlo + c * 128 + g2 * 64 + 32);
                    mma16816(a0, ah0, bh[0], bh[1]);
                    mma16816(a1, al0, bh[0], bh[1]);
                    mma16816(a1, ah0, bl[0], bl[1]);
                    mma16816(a0, ah1, bh[2], bh[3]);
                    mma16816(a1, al1, bh[2], bh[3]);
                    mma16816(a1, ah1, bl[2], bl[3]);
                }
            }

            {
                int gr = wg * 16 + (lane >> 2);
                int gc = wsub * 8 + (lane & 3) * 2;
                gates_s[gr * 33 + gc]           = a0[0] + a1[0];
                gates_s[gr * 33 + gc + 1]       = a0[1] + a1[1];
                gates_s[(gr + 8) * 33 + gc]     = a0[2] + a1[2];
                gates_s[(gr + 8) * 33 + gc + 1] = a0[3] + a1[3];
            }
            __syncthreads();

            {
                float v0 = bias[0] + gates_s[(0 * 16 + lh) * 33 + lb] + gx0;
                float v1 = bias[1] + gates_s[(1 * 16 + lh) * 33 + lb] + gx1;
                float v2 = bias[2] + gates_s[(2 * 16 + lh) * 33 + lb] + gx2;
                float v3 = bias[3] + gates_s[(3 * 16 + lh) * 33 + lb] + gx3;
                float ig = sigf(v0), fg = sigf(v1), gg = tanhg(v2), og = sigf(v3);
                creg = fmaf(fg, creg, ig * gg);
                float hv = og * tanhg(creg);
                g_seq_pack[((size_t)t * 128 + eb) * 512 + egh] = packf(hv);
                if (t == T - 1)
                    out[(size_t)l * BH + (size_t)eb * 512 + egh] = creg;
            }
            gbar_grp(++ep, grp);
        }
    }
}

extern "C" void kernel_launch(void* const* d_in, const int* in_sizes, int n_in,
                              void* d_out, int out_size) {
    const float* x    = (const float*)d_in[0];
    const float* h0   = (const float*)d_in[1];
    const float* c0   = (const float*)d_in[2];
    const float* w_ih = (const float*)d_in[3];
    const float* w_hh = (const float*)d_in[4];
    const float* b_ih = (const float*)d_in[5];
    const float* b_hh = (const float*)d_in[6];
    float* out = (float*)d_out;

    cudaFuncSetAttribute(lstm_kernel,
                         cudaFuncAttributeMaxDynamicSharedMemorySize, SMEM_BYTES);
    lstm_kernel<<<NBLK, NTHR, SMEM_BYTES>>>(x, h0, c0, w_ih, w_hh, b_ih, b_hh, out);
}

// round 10
// speedup vs baseline: 1.6716x; 1.1244x over previous
#include <cuda_runtime.h>
#include <cuda_bf16.h>

#define L 4
#define B 128
#define T 1024
#define NI 512
#define H 512
#define G 2048
#define BH (B*H)

#define NBLK 128
#define NTHR 512

// ---- smem layout (bytes) ----
// W: 64 rows x 512 k, hi/lo bf16 planes, row stride 1040B
#define WS_HI 0
#define WS_LO 66560
// x-phase stage: 2 buffers x (hi+lo planes), plane = 128 rows x 144B
#define PS 133120
#define PLANE 18432
#define BUFSTRIDE 36864
// recurrent stage: 32 rows x 512 k hi/lo planes, row stride 1040B
#define RS 133120
#define RPLANE 33280
// x-phase gates tile (unused in recurrent)
#define GS 206848
#define SMEM_BYTES 215296
// recurrent K-split gate buffers: 4 x (64 x 34 f32) = 34816B, overlaid on W region
// (W_hh lives in registers during the t-loop, so W smem is dead there)
// stride 34 (even) keeps all float2 accesses 8B-aligned.
#define GBUF_STRIDE (64 * 34)

// ---- device scratch ----
__device__ unsigned g_x_pack[(size_t)B * T * NI];
__device__ unsigned g_seq_pack[(size_t)T * BH];
__device__ unsigned g_h0_pack[(size_t)L * BH];
__device__ float g_gx[(size_t)B * T * G];           // [t][b][gate]
__device__ unsigned long long g_flags[NBLK];

__device__ __forceinline__ unsigned long long ldvol(const unsigned long long* p) {
    unsigned long long v;
    asm volatile("ld.volatile.global.u64 %0, [%1];" : "=l"(v) : "l"(p));
    return v;
}

// global barrier (prologue only)
__device__ __forceinline__ void gbar_all(unsigned long long ep) {
    __syncthreads();
    __threadfence();
    if (threadIdx.x == 0) atomicExch(&g_flags[blockIdx.x], ep);
    if (threadIdx.x < NBLK) {
        while (ldvol(&g_flags[threadIdx.x]) < ep) { }
    }
    __threadfence();
    __syncthreads();
}

// group barrier: 32 blocks sharing a batch group
__device__ __forceinline__ void gbar_grp(unsigned long long ep, int grp) {
    __syncthreads();
    __threadfence();
    if (threadIdx.x == 0) atomicExch(&g_flags[blockIdx.x], ep);
    if (threadIdx.x < 32) {
        while (ldvol(&g_flags[grp * 32 + threadIdx.x]) < ep) { }
    }
    __threadfence();
    __syncthreads();
}

__device__ __forceinline__ unsigned packf(float v) {
    __nv_bfloat16 h = __float2bfloat16(v);
    float hf = __bfloat162float(h);
    __nv_bfloat16 lo = __float2bfloat16(v - hf);
    unsigned short uh = *(unsigned short*)&h;
    unsigned short ul = *(unsigned short*)&lo;
    return ((unsigned)ul << 16) | (unsigned)uh;
}

__device__ __forceinline__ void ldsm4(unsigned r[4], unsigned addr) {
    asm volatile("ldmatrix.sync.aligned.m8n8.x4.shared.b16 {%0,%1,%2,%3}, [%4];"
                 : "=r"(r[0]), "=r"(r[1]), "=r"(r[2]), "=r"(r[3]) : "r"(addr));
}

__device__ __forceinline__ void mma16816(float c[4], const unsigned a[4],
                                         unsigned b0, unsigned b1) {
    asm volatile(
        "mma.sync.aligned.m16n8k16.row.col.f32.bf16.bf16.f32 "
        "{%0,%1,%2,%3}, {%4,%5,%6,%7}, {%8,%9}, {%0,%1,%2,%3};"
        : "+f"(c[0]), "+f"(c[1]), "+f"(c[2]), "+f"(c[3])
        : "r"(a[0]), "r"(a[1]), "r"(a[2]), "r"(a[3]), "r"(b0), "r"(b1));
}

__device__ __forceinline__ float sigf(float x) { return 1.0f / (1.0f + __expf(-x)); }
__device__ __forceinline__ float tanhg(float x) { return 2.0f / (1.0f + __expf(-2.0f * x)) - 1.0f; }

__device__ __forceinline__ void stage_store(char* bufHi, unsigned off, uint4 p, int plane) {
    unsigned h0_ = __byte_perm(p.x, p.y, 0x5410);
    unsigned h1_ = __byte_perm(p.z, p.w, 0x5410);
    unsigned l0_ = __byte_perm(p.x, p.y, 0x7632);
    unsigned l1_ = __byte_perm(p.z, p.w, 0x7632);
    *(uint2*)(bufHi + off) = make_uint2(h0_, h1_);
    *(uint2*)(bufHi + plane + off) = make_uint2(l0_, l1_);
}

__global__ void __launch_bounds__(NTHR, 1)
lstm_kernel(const float* __restrict__ x,
            const float* __restrict__ h0,
            const float* __restrict__ c0,
            const float* __restrict__ w_ih,
            const float* __restrict__ w_hh,
            const float* __restrict__ b_ih,
            const float* __restrict__ b_hh,
            float* __restrict__ out) {
    extern __shared__ char sm[];
    const unsigned sbase = (unsigned)__cvta_generic_to_shared(sm);

    const int tid = threadIdx.x, bid = blockIdx.x;
    const int lane = tid & 31, warp = tid >> 5;

    unsigned long long ep = ldvol(&g_flags[bid]);

    // ---------------- prologue: pack x, h0 ----------------
    {
        const size_t gt0 = (size_t)bid * NTHR + tid, gs = (size_t)NBLK * NTHR;
        const float4* xs = (const float4*)x;
        const size_t nx = (size_t)B * T * NI / 4;
        for (size_t i = gt0; i < nx; i += gs) {
            float4 v = __ldg(xs + i);
            ((uint4*)g_x_pack)[i] = make_uint4(packf(v.x), packf(v.y), packf(v.z), packf(v.w));
        }
        const float4* hs = (const float4*)h0;
        const size_t nh = (size_t)L * BH / 4;
        for (size_t i = gt0; i < nh; i += gs) {
            float4 v = __ldg(hs + i);
            ((uint4*)g_h0_pack)[i] = make_uint4(packf(v.x), packf(v.y), packf(v.z), packf(v.w));
        }
    }
    gbar_all(++ep);

    const int gt = bid & 31;    // gate/h tile
    const int grp = bid >> 5;   // batch group (32 batches)

    const int wg = warp >> 2, wsub = warp & 3;
    const unsigned wA = sbase + WS_HI + (unsigned)((wg * 16 + (lane & 15)) * 1040 + (lane >> 4) * 16);
    const unsigned wAlo = wA + (WS_LO - WS_HI);
    const unsigned pBx_rel = (unsigned)((wsub * 32 + (lane & 7) + ((lane >> 4) << 3)) * 144
                                        + ((lane >> 3) & 1) * 16);
    // recurrent B frag base: batch rows (nt*8 added in loop), this warp's K128 slice
    const unsigned pBrK = sbase + RS + (unsigned)((lane & 7) * 1040 + (lane >> 3) * 16 + wsub * 256);

    const int lh = tid & 15, lb = tid >> 4;
    const int eb = grp * 32 + lb;
    const int egh = gt * 16 + lh;

    for (int l = 0; l < L; ++l) {
        // ================= x-phase: gx = W_ih * input_seq =================
        for (int it = tid; it < 64 * 128; it += NTHR) {
            int r = it >> 7, c4 = it & 127;
            float4 v = __ldg((const float4*)(w_ih + ((size_t)l * G + gt * 64 + r) * 512) + c4);
            unsigned p0 = packf(v.x), p1 = packf(v.y), p2 = packf(v.z), p3 = packf(v.w);
            *(uint2*)(sm + WS_HI + r * 1040 + c4 * 8) =
                make_uint2(__byte_perm(p0, p1, 0x5410), __byte_perm(p2, p3, 0x5410));
            *(uint2*)(sm + WS_LO + r * 1040 + c4 * 8) =
                make_uint2(__byte_perm(p0, p1, 0x7632), __byte_perm(p2, p3, 0x7632));
        }
        __syncthreads();

        {
            const int srow = tid >> 2, ssg = tid & 3;
            for (int m = 0; m < 256; ++m) {
                const int bb = grp * 32 + (m >> 3);
                const int t0 = (m & 7) * 128;

                const unsigned* rowp;
                if (l == 0) rowp = g_x_pack + (((size_t)bb << 10) + (size_t)(t0 + srow)) * 512;
                else        rowp = g_seq_pack + ((size_t)((t0 + srow) * 128 + bb)) * 512;

                float acc[4][4];
                #pragma unroll
                for (int f = 0; f < 4; ++f)
                    #pragma unroll
                    for (int q = 0; q < 4; ++q) acc[f][q] = 0.f;

                uint4 rg[4];
                #pragma unroll
                for (int q = 0; q < 4; ++q) rg[q] = __ldcg((const uint4*)rowp + ssg + 4 * q);
                #pragma unroll
                for (int q = 0; q < 4; ++q)
                    stage_store(sm + PS, srow * 144 + (ssg + 4 * q) * 8, rg[q], PLANE);
                #pragma unroll
                for (int q = 0; q < 4; ++q) rg[q] = __ldcg((const uint4*)rowp + 16 + ssg + 4 * q);
                __syncthreads();

                #pragma unroll 1
                for (int c = 0; c < 8; ++c) {
                    if (c < 7) {
                        char* bufHi = sm + PS + ((c + 1) & 1) * BUFSTRIDE;
                        #pragma unroll
                        for (int q = 0; q < 4; ++q)
                            stage_store(bufHi, srow * 144 + (ssg + 4 * q) * 8, rg[q], PLANE);
                    }
                    if (c < 6) {
                        #pragma unroll
                        for (int q = 0; q < 4; ++q)
                            rg[q] = __ldcg((const uint4*)rowp + (c + 2) * 16 + ssg + 4 * q);
                    }
                    const unsigned bufo = sbase + PS + (c & 1) * BUFSTRIDE;
                    #pragma unroll
                    for (int q = 0; q < 4; ++q) {
                        unsigned ah[4], al[4];
                        ldsm4(ah, wA + c * 128 + q * 32);
                        ldsm4(al, wAlo + c * 128 + q * 32);
                        #pragma unroll
                        for (int u = 0; u < 2; ++u) {
                            unsigned bh[4], bl[4];
                            unsigned ba = bufo + pBx_rel + u * 2304 + q * 32;
                            ldsm4(bh, ba);
                            ldsm4(bl, ba + PLANE);
                            mma16816(acc[2 * u],     ah, bh[0], bh[1]);
                            mma16816(acc[2 * u],     al, bh[0], bh[1]);
                            mma16816(acc[2 * u],     ah, bl[0], bl[1]);
                            mma16816(acc[2 * u + 1], ah, bh[2], bh[3]);
                            mma16816(acc[2 * u + 1], al, bh[2], bh[3]);
                            mma16816(acc[2 * u + 1], ah, bl[2], bl[3]);
                        }
                    }
                    __syncthreads();
                }

                // store gx tile: layout [t][b][gate]
                const int gr0g = gt * 64 + wg * 16 + (lane >> 2);
                #pragma unroll
                for (int f = 0; f < 4; ++f) {
                    int u = f >> 1, v2 = f & 1;
                    int tt = wsub * 32 + u * 16 + v2 * 8 + (lane & 3) * 2;
                    size_t base = ((size_t)(t0 + tt) * 128 + bb) * (size_t)G + gr0g;
                    __stcg(g_gx + base,                        acc[f][0]);
                    __stcg(g_gx + base + (size_t)128 * G,      acc[f][1]);
                    __stcg(g_gx + base + 8,                    acc[f][2]);
                    __stcg(g_gx + base + (size_t)128 * G + 8,  acc[f][3]);
                }
            }
        }
        gbar_grp(++ep, grp);

        // ================= recurrent phase =================
        // stage W_hh: local row r -> global gate row (r>>4)*512 + gt*16 + (r&15)
        for (int it = tid; it < 64 * 128; it += NTHR) {
            int r = it >> 7, c4 = it & 127;
            int grow = (r >> 4) * 512 + gt * 16 + (r & 15);
            float4 v = __ldg((const float4*)(w_hh + ((size_t)l * G + grow) * 512) + c4);
            unsigned p0 = packf(v.x), p1 = packf(v.y), p2 = packf(v.z), p3 = packf(v.w);
            *(uint2*)(sm + WS_HI + r * 1040 + c4 * 8) =
                make_uint2(__byte_perm(p0, p1, 0x5410), __byte_perm(p2, p3, 0x5410));
            *(uint2*)(sm + WS_LO + r * 1040 + c4 * 8) =
                make_uint2(__byte_perm(p0, p1, 0x7632), __byte_perm(p2, p3, 0x7632));
        }
        __syncthreads();

        // ---- hoist this warp's W_hh fragments into registers (once per layer) ----
        // warp = (wg m-stripe 16 gates, wsub K-slice of 128); 8 k16-steps, hi+lo
        unsigned ah[8][4], al[8][4];
        #pragma unroll
        for (int c = 0; c < 8; ++c) {
            ldsm4(ah[c], wA + wsub * 256 + c * 32);
            ldsm4(al[c], wAlo + wsub * 256 + c * 32);
        }
        // after this sync the W smem region is dead -> gate buffers overlay it
        __syncthreads();

        float bias[4];
        #pragma unroll
        for (int g = 0; g < 4; ++g)
            bias[g] = __ldg(b_ih + (size_t)l * G + g * 512 + egh)
                    + __ldg(b_hh + (size_t)l * G + g * 512 + egh);
        float creg = __ldg(c0 + (size_t)l * BH + (size_t)eb * 512 + egh);
        const float* gx_base = g_gx + (size_t)eb * G + egh;   // [t][b][gate]

        const int hrow = tid >> 4, hsg = tid & 15;
        float* const gbuf = (float*)sm + wsub * GBUF_STRIDE;
        const int gr = wg * 16 + (lane >> 2);
        const int gc = (lane & 3) * 2;

        for (int t = 0; t < T; ++t) {
            // prefetch gx for EW (hides under MMA phase)
            const float* gxt = gx_base + (size_t)t * (128 * G);
            float gx0 = __ldcg(gxt);
            float gx1 = __ldcg(gxt + 512);
            float gx2 = __ldcg(gxt + 1024);
            float gx3 = __ldcg(gxt + 1536);

            const unsigned* rowp;
            if (t == 0) rowp = g_h0_pack + ((size_t)(l * 128 + grp * 32 + hrow)) * 512;
            else        rowp = g_seq_pack + ((size_t)((t - 1) * 128 + grp * 32 + hrow)) * 512;

            uint4 hrg[8];
            #pragma unroll
            for (int c = 0; c < 8; ++c)
                hrg[c] = __ldcg((const uint4*)rowp + c * 16 + hsg);

            #pragma unroll
            for (int c = 0; c < 8; ++c)
                stage_store(sm + RS, hrow * 1040 + (c * 16 + hsg) * 8, hrg[c], RPLANE);
            __syncthreads();

            // warp computes m16 x n32 over its K128 slice; A from registers, B-only ldsm
            float a0[4][4], a1[4][4];
            #pragma unroll
            for (int nt = 0; nt < 4; ++nt)
                #pragma unroll
                for (int q = 0; q < 4; ++q) { a0[nt][q] = 0.f; a1[nt][q] = 0.f; }

            #pragma unroll
            for (int nt = 0; nt < 4; ++nt) {
                const unsigned bbase = pBrK + nt * (8 * 1040);
                #pragma unroll
                for (int c2 = 0; c2 < 4; ++c2) {
                    unsigned bh[4], bl[4];
                    ldsm4(bh, bbase + c2 * 64);
                    ldsm4(bl, bbase + c2 * 64 + RPLANE);
                    mma16816(a0[nt], ah[2 * c2],     bh[0], bh[1]);
                    mma16816(a1[nt], al[2 * c2],     bh[0], bh[1]);
                    mma16816(a1[nt], ah[2 * c2],     bl[0], bl[1]);
                    mma16816(a0[nt], ah[2 * c2 + 1], bh[2], bh[3]);
                    mma16816(a1[nt], al[2 * c2 + 1], bh[2], bh[3]);
                    mma16816(a1[nt], ah[2 * c2 + 1], bl[2], bl[3]);
                }
            }

            // K-split partials -> per-wsub gate buffer (no RMW, all warps parallel)
            #pragma unroll
            for (int nt = 0; nt < 4; ++nt) {
                *(float2*)&gbuf[gr * 34 + nt * 8 + gc] =
                    make_float2(a0[nt][0] + a1[nt][0], a0[nt][1] + a1[nt][1]);
                *(float2*)&gbuf[(gr + 8) * 34 + nt * 8 + gc] =
                    make_float2(a0[nt][2] + a1[nt][2], a0[nt][3] + a1[nt][3]);
            }
            __syncthreads();

            // elementwise: sum 4 K-split buffers + gx + bias
            {
                float v0 = bias[0] + gx0;
                float v1 = bias[1] + gx1;
                float v2 = bias[2] + gx2;
                float v3 = bias[3] + gx3;
                #pragma unroll
                for (int s = 0; s < 4; ++s) {
                    const float* gb = (const float*)sm + s * GBUF_STRIDE;
                    v0 += gb[(0 * 16 + lh) * 34 + lb];
                    v1 += gb[(1 * 16 + lh) * 34 + lb];
                    v2 += gb[(2 * 16 + lh) * 34 + lb];
                    v3 += gb[(3 * 16 + lh) * 34 + lb];
                }
                float ig = sigf(v0), fg = sigf(v1), gg = tanhg(v2), og = sigf(v3);
                creg = fmaf(fg, creg, ig * gg);
                float hv = og * tanhg(creg);
                g_seq_pack[((size_t)t * 128 + eb) * 512 + egh] = packf(hv);
                if (t == T - 1)
                    out[(size_t)l * BH + (size_t)eb * 512 + egh] = creg;
            }
            gbar_grp(++ep, grp);
        }
    }
}

extern "C" void kernel_launch(void* const* d_in, const int* in_sizes, int n_in,
                              void* d_out, int out_size) {
    const float* x    = (const float*)d_in[0];
    const float* h0   = (const float*)d_in[1];
    const float* c0   = (const float*)d_in[2];
    const float* w_ih = (const float*)d_in[3];
    const float* w_hh = (const float*)d_in[4];
    const float* b_ih = (const float*)d_in[5];
    const float* b_hh = (const float*)d_in[6];
    float* out = (float*)d_out;

    cudaFuncSetAttribute(lstm_kernel,
                         cudaFuncAttributeMaxDynamicSharedMemorySize, SMEM_BYTES);
    lstm_kernel<<<NBLK, NTHR, SMEM_BYTES>>>(x, h0, c0, w_ih, w_hh, b_ih, b_hh, out);
}

// round 11
// speedup vs baseline: 1.8695x; 1.1184x over previous
#include <cuda_runtime.h>
#include <cuda_bf16.h>

#define L 4
#define B 128
#define T 1024
#define NI 512
#define H 512
#define G 2048
#define BH (B*H)

#define NBLK 128
#define NTHR 512

// ---- smem layout (bytes) ----
// W: 64 rows x 512 k, hi/lo bf16 planes, row stride 1040B
#define WS_HI 0
#define WS_LO 66560
// x-phase stage: 2 buffers x (hi+lo planes), plane = 128 rows x 144B
#define PS 133120
#define PLANE 18432
#define BUFSTRIDE 36864
// recurrent stage: 32 rows x 512 k hi/lo planes, row stride 1040B
#define RS 133120
#define RPLANE 33280
#define GS 206848
#define SMEM_BYTES 215296
// recurrent K-split gate buffers: 4 x (64 x 34 f32) = 34816B, overlaid on W region
#define GBUF_STRIDE (64 * 34)

// ---- device scratch: pre-split hi/lo bf16 planes ----
__device__ __nv_bfloat16 g_x_hi[(size_t)B * T * NI];    // [b][t][k]
__device__ __nv_bfloat16 g_x_lo[(size_t)B * T * NI];
__device__ __nv_bfloat16 g_seq_hi[(size_t)T * BH];      // [t][b][k]
__device__ __nv_bfloat16 g_seq_lo[(size_t)T * BH];
__device__ __nv_bfloat16 g_h0_hi[(size_t)L * BH];
__device__ __nv_bfloat16 g_h0_lo[(size_t)L * BH];
__device__ float g_gx[(size_t)B * T * G];               // [t][b][gate]
__device__ unsigned long long g_flags[NBLK];

#define CP_ASYNC16(dst, src) \
    asm volatile("cp.async.cg.shared.global [%0], [%1], 16;" :: "r"(dst), "l"(src))
#define CP_COMMIT() asm volatile("cp.async.commit_group;" ::: "memory")
#define CP_WAIT0()  asm volatile("cp.async.wait_group 0;" ::: "memory")

__device__ __forceinline__ unsigned long long ldvol(const unsigned long long* p) {
    unsigned long long v;
    asm volatile("ld.volatile.global.u64 %0, [%1];" : "=l"(v) : "l"(p));
    return v;
}

// global barrier (prologue only)
__device__ __forceinline__ void gbar_all(unsigned long long ep) {
    __syncthreads();
    __threadfence();
    if (threadIdx.x == 0) atomicExch(&g_flags[blockIdx.x], ep);
    if (threadIdx.x < NBLK) {
        while (ldvol(&g_flags[threadIdx.x]) < ep) { }
    }
    __threadfence();
    __syncthreads();
}

// group barrier: 32 blocks sharing a batch group
__device__ __forceinline__ void gbar_grp(unsigned long long ep, int grp) {
    __syncthreads();
    __threadfence();
    if (threadIdx.x == 0) atomicExch(&g_flags[blockIdx.x], ep);
    if (threadIdx.x < 32) {
        while (ldvol(&g_flags[grp * 32 + threadIdx.x]) < ep) { }
    }
    __threadfence();
    __syncthreads();
}

// fp32x4 -> hi/lo bf16 plane pairs (uint2 = 4 bf16)
__device__ __forceinline__ void split4(float4 v, uint2& hi, uint2& lo) {
    __nv_bfloat16 h0 = __float2bfloat16(v.x), h1 = __float2bfloat16(v.y);
    __nv_bfloat16 h2 = __float2bfloat16(v.z), h3 = __float2bfloat16(v.w);
    __nv_bfloat16 l0 = __float2bfloat16(v.x - __bfloat162float(h0));
    __nv_bfloat16 l1 = __float2bfloat16(v.y - __bfloat162float(h1));
    __nv_bfloat16 l2 = __float2bfloat16(v.z - __bfloat162float(h2));
    __nv_bfloat16 l3 = __float2bfloat16(v.w - __bfloat162float(h3));
    hi.x = (unsigned)*(unsigned short*)&h0 | ((unsigned)*(unsigned short*)&h1 << 16);
    hi.y = (unsigned)*(unsigned short*)&h2 | ((unsigned)*(unsigned short*)&h3 << 16);
    lo.x = (unsigned)*(unsigned short*)&l0 | ((unsigned)*(unsigned short*)&l1 << 16);
    lo.y = (unsigned)*(unsigned short*)&l2 | ((unsigned)*(unsigned short*)&l3 << 16);
}

__device__ __forceinline__ void ldsm4(unsigned r[4], unsigned addr) {
    asm volatile("ldmatrix.sync.aligned.m8n8.x4.shared.b16 {%0,%1,%2,%3}, [%4];"
                 : "=r"(r[0]), "=r"(r[1]), "=r"(r[2]), "=r"(r[3]) : "r"(addr));
}

__device__ __forceinline__ void mma16816(float c[4], const unsigned a[4],
                                         unsigned b0, unsigned b1) {
    asm volatile(
        "mma.sync.aligned.m16n8k16.row.col.f32.bf16.bf16.f32 "
        "{%0,%1,%2,%3}, {%4,%5,%6,%7}, {%8,%9}, {%0,%1,%2,%3};"
        : "+f"(c[0]), "+f"(c[1]), "+f"(c[2]), "+f"(c[3])
        : "r"(a[0]), "r"(a[1]), "r"(a[2]), "r"(a[3]), "r"(b0), "r"(b1));
}

__device__ __forceinline__ float sigf(float x) { return 1.0f / (1.0f + __expf(-x)); }
__device__ __forceinline__ float tanhg(float x) { return 2.0f / (1.0f + __expf(-2.0f * x)) - 1.0f; }

__global__ void __launch_bounds__(NTHR, 1)
lstm_kernel(const float* __restrict__ x,
            const float* __restrict__ h0,
            const float* __restrict__ c0,
            const float* __restrict__ w_ih,
            const float* __restrict__ w_hh,
            const float* __restrict__ b_ih,
            const float* __restrict__ b_hh,
            float* __restrict__ out) {
    extern __shared__ char sm[];
    const unsigned sbase = (unsigned)__cvta_generic_to_shared(sm);

    const int tid = threadIdx.x, bid = blockIdx.x;
    const int lane = tid & 31, warp = tid >> 5;

    unsigned long long ep = ldvol(&g_flags[bid]);

    // ---------------- prologue: split x, h0 into hi/lo planes ----------------
    {
        const size_t gt0 = (size_t)bid * NTHR + tid, gs = (size_t)NBLK * NTHR;
        const float4* xs = (const float4*)x;
        const size_t nx = (size_t)B * T * NI / 4;
        for (size_t i = gt0; i < nx; i += gs) {
            uint2 hi, lo;
            split4(__ldg(xs + i), hi, lo);
            ((uint2*)g_x_hi)[i] = hi;
            ((uint2*)g_x_lo)[i] = lo;
        }
        const float4* hs = (const float4*)h0;
        const size_t nh = (size_t)L * BH / 4;
        for (size_t i = gt0; i < nh; i += gs) {
            uint2 hi, lo;
            split4(__ldg(hs + i), hi, lo);
            ((uint2*)g_h0_hi)[i] = hi;
            ((uint2*)g_h0_lo)[i] = lo;
        }
    }
    gbar_all(++ep);

    const int gt = bid & 31;    // gate/h tile
    const int grp = bid >> 5;   // batch group (32 batches)

    const int wg = warp >> 2, wsub = warp & 3;
    const unsigned wA = sbase + WS_HI + (unsigned)((wg * 16 + (lane & 15)) * 1040 + (lane >> 4) * 16);
    const unsigned wAlo = wA + (WS_LO - WS_HI);
    const unsigned pBx_rel = (unsigned)((wsub * 32 + (lane & 7) + ((lane >> 4) << 3)) * 144
                                        + ((lane >> 3) & 1) * 16);
    const unsigned pBrK = sbase + RS + (unsigned)((lane & 7) * 1040 + (lane >> 3) * 16 + wsub * 256);

    const int lh = tid & 15, lb = tid >> 4;
    const int eb = grp * 32 + lb;
    const int egh = gt * 16 + lh;

    // x-phase stage mapping: 2 chunks/thread/plane; chunk id cc -> row = cc>>3, seg = cc&7
    const int xr0 = tid >> 3, xs0 = tid & 7;          // cc = tid
    const int xr1 = (tid + 512) >> 3, xs1 = tid & 7;  // cc = tid + 512
    // recurrent stage mapping: 4 chunks/thread/plane; cc -> row = cc>>6, seg = cc&63
    const int rr0 = tid >> 6, rsg = tid & 63;

    for (int l = 0; l < L; ++l) {
        // ================= x-phase: gx = W_ih * input_seq =================
        for (int it = tid; it < 64 * 128; it += NTHR) {
            int r = it >> 7, c4 = it & 127;
            float4 v = __ldg((const float4*)(w_ih + ((size_t)l * G + gt * 64 + r) * 512) + c4);
            uint2 hi, lo;
            split4(v, hi, lo);
            *(uint2*)(sm + WS_HI + r * 1040 + c4 * 8) = hi;
            *(uint2*)(sm + WS_LO + r * 1040 + c4 * 8) = lo;
        }
        __syncthreads();

        {
            for (int m = 0; m < 256; ++m) {
                const int bb = grp * 32 + (m >> 3);
                const int t0 = (m & 7) * 128;

                // row element base addresses for this m-iter (per staged row)
                const __nv_bfloat16 *hiP, *loP;
                size_t rb0, rb1;   // element offsets of rows xr0, xr1
                if (l == 0) {
                    hiP = g_x_hi; loP = g_x_lo;
                    rb0 = (((size_t)bb << 10) + (size_t)(t0 + xr0)) * 512;
                    rb1 = (((size_t)bb << 10) + (size_t)(t0 + xr1)) * 512;
                } else {
                    hiP = g_seq_hi; loP = g_seq_lo;
                    rb0 = ((size_t)((t0 + xr0) * 128 + bb)) * 512;
                    rb1 = ((size_t)((t0 + xr1) * 128 + bb)) * 512;
                }

                float acc[4][4];
                #pragma unroll
                for (int f = 0; f < 4; ++f)
                    #pragma unroll
                    for (int q = 0; q < 4; ++q) acc[f][q] = 0.f;

                // issue chunk 0 -> buf0
                {
                    const unsigned d0 = sbase + PS + xr0 * 144 + xs0 * 16;
                    const unsigned d1 = sbase + PS + xr1 * 144 + xs1 * 16;
                    CP_ASYNC16(d0,          hiP + rb0 + xs0 * 8);
                    CP_ASYNC16(d0 + PLANE,  loP + rb0 + xs0 * 8);
                    CP_ASYNC16(d1,          hiP + rb1 + xs1 * 8);
                    CP_ASYNC16(d1 + PLANE,  loP + rb1 + xs1 * 8);
                    CP_COMMIT();
                }

                #pragma unroll 1
                for (int c = 0; c < 8; ++c) {
                    CP_WAIT0();
                    __syncthreads();
                    if (c < 7) {
                        const int k0 = (c + 1) * 64;
                        const unsigned bufd = sbase + PS + ((c + 1) & 1) * BUFSTRIDE;
                        const unsigned d0 = bufd + xr0 * 144 + xs0 * 16;
                        const unsigned d1 = bufd + xr1 * 144 + xs1 * 16;
                        CP_ASYNC16(d0,          hiP + rb0 + k0 + xs0 * 8);
                        CP_ASYNC16(d0 + PLANE,  loP + rb0 + k0 + xs0 * 8);
                        CP_ASYNC16(d1,          hiP + rb1 + k0 + xs1 * 8);
                        CP_ASYNC16(d1 + PLANE,  loP + rb1 + k0 + xs1 * 8);
                        CP_COMMIT();
                    }
                    const unsigned bufo = sbase + PS + (c & 1) * BUFSTRIDE;
                    #pragma unroll
                    for (int q = 0; q < 4; ++q) {
                        unsigned ah[4], al[4];
                        ldsm4(ah, wA + c * 128 + q * 32);
                        ldsm4(al, wAlo + c * 128 + q * 32);
                        #pragma unroll
                        for (int u = 0; u < 2; ++u) {
                            unsigned bh[4], bl[4];
                            unsigned ba = bufo + pBx_rel + u * 2304 + q * 32;
                            ldsm4(bh, ba);
                            ldsm4(bl, ba + PLANE);
                            mma16816(acc[2 * u],     ah, bh[0], bh[1]);
                            mma16816(acc[2 * u],     al, bh[0], bh[1]);
                            mma16816(acc[2 * u],     ah, bl[0], bl[1]);
                            mma16816(acc[2 * u + 1], ah, bh[2], bh[3]);
                            mma16816(acc[2 * u + 1], al, bh[2], bh[3]);
                            mma16816(acc[2 * u + 1], ah, bl[2], bl[3]);
                        }
                    }
                }

                // store gx tile: layout [t][b][gate]
                const int gr0g = gt * 64 + wg * 16 + (lane >> 2);
                #pragma unroll
                for (int f = 0; f < 4; ++f) {
                    int u = f >> 1, v2 = f & 1;
                    int tt = wsub * 32 + u * 16 + v2 * 8 + (lane & 3) * 2;
                    size_t base = ((size_t)(t0 + tt) * 128 + bb) * (size_t)G + gr0g;
                    __stcg(g_gx + base,                        acc[f][0]);
                    __stcg(g_gx + base + (size_t)128 * G,      acc[f][1]);
                    __stcg(g_gx + base + 8,                    acc[f][2]);
                    __stcg(g_gx + base + (size_t)128 * G + 8,  acc[f][3]);
                }
                __syncthreads();   // protect buf0 before next m-iter's chunk-0 issue
            }
        }
        gbar_grp(++ep, grp);

        // ================= recurrent phase =================
        // stage W_hh: local row r -> global gate row (r>>4)*512 + gt*16 + (r&15)
        for (int it = tid; it < 64 * 128; it += NTHR) {
            int r = it >> 7, c4 = it & 127;
            int grow = (r >> 4) * 512 + gt * 16 + (r & 15);
            float4 v = __ldg((const float4*)(w_hh + ((size_t)l * G + grow) * 512) + c4);
            uint2 hi, lo;
            split4(v, hi, lo);
            *(uint2*)(sm + WS_HI + r * 1040 + c4 * 8) = hi;
            *(uint2*)(sm + WS_LO + r * 1040 + c4 * 8) = lo;
        }
        __syncthreads();

        // hoist this warp's W_hh fragments into registers (once per layer)
        unsigned ah[8][4], al[8][4];
        #pragma unroll
        for (int c = 0; c < 8; ++c) {
            ldsm4(ah[c], wA + wsub * 256 + c * 32);
            ldsm4(al[c], wAlo + wsub * 256 + c * 32);
        }
        __syncthreads();   // W smem now dead -> gate buffers overlay it

        float bias[4];
        #pragma unroll
        for (int g = 0; g < 4; ++g)
            bias[g] = __ldg(b_ih + (size_t)l * G + g * 512 + egh)
                    + __ldg(b_hh + (size_t)l * G + g * 512 + egh);
        float creg = __ldg(c0 + (size_t)l * BH + (size_t)eb * 512 + egh);
        const float* gx_base = g_gx + (size_t)eb * G + egh;   // [t][b][gate]

        float* const gbuf = (float*)sm + wsub * GBUF_STRIDE;
        const int gr = wg * 16 + (lane >> 2);
        const int gc = (lane & 3) * 2;

        for (int t = 0; t < T; ++t) {
            // stage h(t-1) tile via cp.async: 4 chunks/thread/plane
            {
                const __nv_bfloat16 *hiP, *loP;
                size_t rowe;   // element offset of row rr0 (+8 rows per i)
                if (t == 0) {
                    hiP = g_h0_hi; loP = g_h0_lo;
                    rowe = ((size_t)(l * 128 + grp * 32 + rr0)) * 512;
                } else {
                    hiP = g_seq_hi; loP = g_seq_lo;
                    rowe = ((size_t)((t - 1) * 128 + grp * 32 + rr0)) * 512;
                }
                #pragma unroll
                for (int i = 0; i < 4; ++i) {
                    const unsigned d = sbase + RS + (rr0 + i * 8) * 1040 + rsg * 16;
                    const size_t s = rowe + (size_t)(i * 8) * 512 + rsg * 8;
                    CP_ASYNC16(d,          hiP + s);
                    CP_ASYNC16(d + RPLANE, loP + s);
                }
                CP_COMMIT();
            }

            // prefetch gx for EW (during the copy)
            const float* gxt = gx_base + (size_t)t * (128 * G);
            float gx0 = __ldcg(gxt);
            float gx1 = __ldcg(gxt + 512);
            float gx2 = __ldcg(gxt + 1024);
            float gx3 = __ldcg(gxt + 1536);

            CP_WAIT0();
            __syncthreads();

            // warp computes m16 x n32 over its K128 slice; A from registers, B-only ldsm
            float a0[4][4], a1[4][4];
            #pragma unroll
            for (int nt = 0; nt < 4; ++nt)
                #pragma unroll
                for (int q = 0; q < 4; ++q) { a0[nt][q] = 0.f; a1[nt][q] = 0.f; }

            #pragma unroll
            for (int nt = 0; nt < 4; ++nt) {
                const unsigned bbase = pBrK + nt * (8 * 1040);
                #pragma unroll
                for (int c2 = 0; c2 < 4; ++c2) {
                    unsigned bh[4], bl[4];
                    ldsm4(bh, bbase + c2 * 64);
                    ldsm4(bl, bbase + c2 * 64 + RPLANE);
                    mma16816(a0[nt], ah[2 * c2],     bh[0], bh[1]);
                    mma16816(a1[nt], al[2 * c2],     bh[0], bh[1]);
                    mma16816(a1[nt], ah[2 * c2],     bl[0], bl[1]);
                    mma16816(a0[nt], ah[2 * c2 + 1], bh[2], bh[3]);
                    mma16816(a1[nt], al[2 * c2 + 1], bh[2], bh[3]);
                    mma16816(a1[nt], ah[2 * c2 + 1], bl[2], bl[3]);
                }
            }

            // K-split partials -> per-wsub gate buffer
            #pragma unroll
            for (int nt = 0; nt < 4; ++nt) {
                *(float2*)&gbuf[gr * 34 + nt * 8 + gc] =
                    make_float2(a0[nt][0] + a1[nt][0], a0[nt][1] + a1[nt][1]);
                *(float2*)&gbuf[(gr + 8) * 34 + nt * 8 + gc] =
                    make_float2(a0[nt][2] + a1[nt][2], a0[nt][3] + a1[nt][3]);
            }
            __syncthreads();

            // elementwise: sum 4 K-split buffers + gx + bias
            {
                float v0 = bias[0] + gx0;
                float v1 = bias[1] + gx1;
                float v2 = bias[2] + gx2;
                float v3 = bias[3] + gx3;
                #pragma unroll
                for (int s = 0; s < 4; ++s) {
                    const float* gb = (const float*)sm + s * GBUF_STRIDE;
                    v0 += gb[(0 * 16 + lh) * 34 + lb];
                    v1 += gb[(1 * 16 + lh) * 34 + lb];
                    v2 += gb[(2 * 16 + lh) * 34 + lb];
                    v3 += gb[(3 * 16 + lh) * 34 + lb];
                }
                float ig = sigf(v0), fg = sigf(v1), gg = tanhg(v2), og = sigf(v3);
                creg = fmaf(fg, creg, ig * gg);
                float hv = og * tanhg(creg);
                size_t hidx = ((size_t)t * 128 + eb) * 512 + egh;
                __nv_bfloat16 hb = __float2bfloat16(hv);
                __nv_bfloat16 hl = __float2bfloat16(hv - __bfloat162float(hb));
                g_seq_hi[hidx] = hb;
                g_seq_lo[hidx] = hl;
                if (t == T - 1)
                    out[(size_t)l * BH + (size_t)eb * 512 + egh] = creg;
            }
            gbar_grp(++ep, grp);
        }
    }
}

extern "C" void kernel_launch(void* const* d_in, const int* in_sizes, int n_in,
                              void* d_out, int out_size) {
    const float* x    = (const float*)d_in[0];
    const float* h0   = (const float*)d_in[1];
    const float* c0   = (const float*)d_in[2];
    const float* w_ih = (const float*)d_in[3];
    const float* w_hh = (const float*)d_in[4];
    const float* b_ih = (const float*)d_in[5];
    const float* b_hh = (const float*)d_in[6];
    float* out = (float*)d_out;

    cudaFuncSetAttribute(lstm_kernel,
                         cudaFuncAttributeMaxDynamicSharedMemorySize, SMEM_BYTES);
    lstm_kernel<<<NBLK, NTHR, SMEM_BYTES>>>(x, h0, c0, w_ih, w_hh, b_ih, b_hh, out);
}